// round 2
// baseline (speedup 1.0000x reference)
#include <cuda_runtime.h>
#include <math.h>

// Problem caps (N=100000, E=1600000 per spec; margin added)
#define MAXN 131072
#define MAXE 1700000

__device__ float2 d_gc[MAXN];      // per node: (g = coef * s.attn_w, coef)
__device__ int    d_deg[MAXN];
__device__ int    d_start[MAXN];
__device__ int    d_cur[MAXN];
__device__ int    d_srcs[MAXE];    // edge sources grouped by target (CSR)
__device__ int    d_bsum[1024];

__device__ __forceinline__ float warpSum(float v) {
#pragma unroll
    for (int o = 16; o > 0; o >>= 1) v += __shfl_xor_sync(0xffffffffu, v, o);
    return v;
}

// ---------------------------------------------------------------------------
// Zero counters
__global__ void k_zero(int n) {
    int i = blockIdx.x * blockDim.x + threadIdx.x;
    if (i < n) { d_deg[i] = 0; d_cur[i] = 0; }
}

// ---------------------------------------------------------------------------
// Per-node precompute: g[i] = coef_i * (s_i . attn_w), coef_i = acosh(x0)/||s||
// One warp per node; lane holds dims (2*lane, 2*lane+1).
__global__ void k_pre(const float* __restrict__ x, const float* __restrict__ aw, int n) {
    int w = (blockIdx.x * blockDim.x + threadIdx.x) >> 5;
    int lane = threadIdx.x & 31;
    if (w >= n) return;
    float2 v = *reinterpret_cast<const float2*>(x + (size_t)w * 64 + lane * 2);
    float dotw, sn;
    if (lane == 0) {            // dim0 = time coordinate: excluded from both
        dotw = v.y * aw[0];
        sn   = v.y * v.y;
    } else {
        dotw = v.x * aw[2 * lane - 1] + v.y * aw[2 * lane];
        sn   = v.x * v.x + v.y * v.y;
    }
    dotw = warpSum(dotw);
    sn   = warpSum(sn);
    float x0   = __shfl_sync(0xffffffffu, v.x, 0);
    float dist = acoshf(fmaxf(x0, 1.0f + 1e-7f));
    float un   = sqrtf(fmaxf(sn, 1e-12f));
    float coef = dist / un;
    if (lane == 0) d_gc[w] = make_float2(coef * dotw, coef);
}

// ---------------------------------------------------------------------------
// CSR build: count, scan (3 kernels), scatter
__global__ void k_count(const int* __restrict__ ei, int E) {
    int e = blockIdx.x * blockDim.x + threadIdx.x;
    if (e < E) atomicAdd(&d_deg[ei[E + e]], 1);
}

__global__ void k_bsum(int n) {
    __shared__ int sh[1024];
    int t = threadIdx.x;
    int i = blockIdx.x * 1024 + t;
    int v = (i < n) ? d_deg[i] : 0;
    sh[t] = v;
    __syncthreads();
    for (int off = 1; off < 1024; off <<= 1) {
        int u = (t >= off) ? sh[t - off] : 0;
        __syncthreads();
        sh[t] += u;
        __syncthreads();
    }
    if (t == 1023) d_bsum[blockIdx.x] = sh[1023];
}

__global__ void k_scanb(int nb) {
    __shared__ int sh[1024];
    int t = threadIdx.x;
    int v = (t < nb) ? d_bsum[t] : 0;
    sh[t] = v;
    __syncthreads();
    for (int off = 1; off < 1024; off <<= 1) {
        int u = (t >= off) ? sh[t - off] : 0;
        __syncthreads();
        sh[t] += u;
        __syncthreads();
    }
    if (t < nb) d_bsum[t] = sh[t] - v;   // exclusive
}

__global__ void k_start(int n) {
    __shared__ int sh[1024];
    int t = threadIdx.x;
    int i = blockIdx.x * 1024 + t;
    int v = (i < n) ? d_deg[i] : 0;
    sh[t] = v;
    __syncthreads();
    for (int off = 1; off < 1024; off <<= 1) {
        int u = (t >= off) ? sh[t - off] : 0;
        __syncthreads();
        sh[t] += u;
        __syncthreads();
    }
    if (i < n) d_start[i] = d_bsum[blockIdx.x] + (sh[t] - v);
}

__global__ void k_scatter(const int* __restrict__ ei, int E) {
    int e = blockIdx.x * blockDim.x + threadIdx.x;
    if (e < E) {
        int r = ei[e];
        int c = ei[E + e];
        int pos = d_start[c] + atomicAdd(&d_cur[c], 1);
        d_srcs[pos] = r;
    }
}

// ---------------------------------------------------------------------------
// Main aggregation: one warp per target node. Online softmax over its edges,
// register-resident 64-dim accumulators (float2 per lane), then epilogue.
__global__ void k_agg(const float* __restrict__ x, float* __restrict__ out, int n) {
    int node = (blockIdx.x * blockDim.x + threadIdx.x) >> 5;
    int lane = threadIdx.x & 31;
    if (node >= n) return;

    int s0 = d_start[node];
    int s1 = s0 + d_deg[node];

    float gcol = d_gc[node].x;
    float m = -INFINITY;
    float z = 0.0f;
    float2 A = make_float2(0.0f, 0.0f);   // sum e * x_src
    float2 T = make_float2(0.0f, 0.0f);   // sum e * coef_src * x_src (tangent)

    for (int e = s0; e < s1; ++e) {
        int src = d_srcs[e];                          // broadcast load
        float2 gs = d_gc[src];                        // (g, coef), broadcast
        float sc = gcol + gs.x;
        if (sc > m) {                                 // warp-uniform branch
            float r = expf(m - sc);                   // exp(-inf)=0 first time
            z *= r; A.x *= r; A.y *= r; T.x *= r; T.y *= r;
            m = sc;
        }
        float w = expf(sc - m);
        z += w;
        float2 v = *reinterpret_cast<const float2*>(x + (size_t)src * 64 + lane * 2);
        A.x += w * v.x;  A.y += w * v.y;
        float wc = w * gs.y;
        T.x += wc * v.x; T.y += wc * v.y;
    }

    bool isolated = (s1 == s0);
    float invz = isolated ? 0.0f : (1.0f / z);        // z >= 1 when edges exist

    float2 agg = make_float2(A.x * invz, A.y * invz);
    float2 tan = make_float2(T.x * invz, T.y * invz);
    if (lane == 0) tan.x = 0.0f;                      // time component of tangent is 0

    // nsq = -<agg,agg>_L = agg0^2 - sum(spatial^2)
    float c = agg.x * agg.x + agg.y * agg.y;
    if (lane == 0) c = -agg.x * agg.x + agg.y * agg.y;
    float mdot = warpSum(c);
    float nsq = -mdot;
    bool non_timelike = (nsq <= 1e-8f);

    // tangent fallback: fb = cosh(vn)*e0 + sinh(vn)/vn * tan
    float t2 = tan.x * tan.x + tan.y * tan.y;
    float vnsq = warpSum(t2);
    float vn = sqrtf(fmaxf(vnsq, 1e-15f));
    float sh = sinhf(vn) / vn;
    float ch = coshf(vn);
    float2 fb = make_float2(sh * tan.x, sh * tan.y);
    if (lane == 0) fb.x = ch;

    float2 a2 = non_timelike ? fb : agg;

    float c2 = a2.x * a2.x + a2.y * a2.y;
    if (lane == 0) c2 = -a2.x * a2.x + a2.y * a2.y;
    float mdot2 = warpSum(c2);
    float nsq2 = -mdot2;
    float denom = fmaxf(sqrtf(fmaxf(nsq2, 0.0f)), 1e-12f);
    float inv = 1.0f / denom;

    float a20 = __shfl_sync(0xffffffffu, a2.x, 0);
    float fac = (a20 <= 0.0f) ? -inv : inv;           // upper-sheet correction

    float2 o = make_float2(a2.x * fac, a2.y * fac);
    *reinterpret_cast<float2*>(out + (size_t)node * 64 + lane * 2) = o;
}

// ---------------------------------------------------------------------------
extern "C" void kernel_launch(void* const* d_in, const int* in_sizes, int n_in,
                              void* d_out, int out_size) {
    const float* x  = (const float*)d_in[0];
    const int*   ei = (const int*)d_in[1];
    const float* aw = (const float*)d_in[2];
    float* out = (float*)d_out;

    int N = in_sizes[0] / 64;
    int E = in_sizes[1] / 2;
    int nb = (N + 1023) / 1024;

    k_zero   <<<(N + 255) / 256, 256>>>(N);
    k_pre    <<<(N + 7) / 8,     256>>>(x, aw, N);
    k_count  <<<(E + 255) / 256, 256>>>(ei, E);
    k_bsum   <<<nb,             1024>>>(N);
    k_scanb  <<<1,              1024>>>(nb);
    k_start  <<<nb,             1024>>>(N);
    k_scatter<<<(E + 255) / 256, 256>>>(ei, E);
    k_agg    <<<(N + 7) / 8,     256>>>(x, out, N);
}

// round 3
// speedup vs baseline: 1.2532x; 1.2532x over previous
#include <cuda_runtime.h>
#include <math.h>

#define MAXN 131072
#define MAXE 1700000

__device__ float2 d_gc[MAXN];      // per node: (g = coef * s.attn_w, coef)
__device__ int    d_deg[MAXN];
__device__ int    d_start[MAXN];
__device__ int    d_cur[MAXN];
__device__ int    d_srcs[MAXE];    // edge sources grouped by target (CSR)
__device__ int    d_bsum[1024];

__device__ __forceinline__ float warpSumF(float v) {
#pragma unroll
    for (int o = 16; o > 0; o >>= 1) v += __shfl_xor_sync(0xffffffffu, v, o);
    return v;
}
__device__ __forceinline__ float warpMaxF(float v) {
#pragma unroll
    for (int o = 16; o > 0; o >>= 1) v = fmaxf(v, __shfl_xor_sync(0xffffffffu, v, o));
    return v;
}
__device__ __forceinline__ int warpSumI(int v) {
#pragma unroll
    for (int o = 16; o > 0; o >>= 1) v += __shfl_xor_sync(0xffffffffu, v, o);
    return v;
}
__device__ __forceinline__ int warpIncScan(int v, int lane) {
#pragma unroll
    for (int o = 1; o < 32; o <<= 1) {
        int u = __shfl_up_sync(0xffffffffu, v, o);
        if (lane >= o) v += u;
    }
    return v;
}

// ---------------------------------------------------------------------------
// Per-node precompute (+ zero counters): g[i] = coef_i * (s_i . attn_w)
__global__ void k_pre(const float* __restrict__ x, const float* __restrict__ aw, int n) {
    int w = (blockIdx.x * blockDim.x + threadIdx.x) >> 5;
    int lane = threadIdx.x & 31;
    if (w >= n) return;
    float2 v = *reinterpret_cast<const float2*>(x + (size_t)w * 64 + lane * 2);
    float dotw, sn;
    if (lane == 0) {            // dim0 = time coordinate: excluded from both
        dotw = v.y * aw[0];
        sn   = v.y * v.y;
    } else {
        dotw = v.x * aw[2 * lane - 1] + v.y * aw[2 * lane];
        sn   = v.x * v.x + v.y * v.y;
    }
    dotw = warpSumF(dotw);
    sn   = warpSumF(sn);
    float x0   = __shfl_sync(0xffffffffu, v.x, 0);
    float dist = acoshf(fmaxf(x0, 1.0f + 1e-7f));
    float un   = sqrtf(fmaxf(sn, 1e-12f));
    float coef = dist / un;
    if (lane == 0) {
        d_gc[w] = make_float2(coef * dotw, coef);
        d_deg[w] = 0;
        d_cur[w] = 0;
    }
}

// ---------------------------------------------------------------------------
// CSR build
__global__ void k_count(const int* __restrict__ ei, int E) {
    int e = blockIdx.x * blockDim.x + threadIdx.x;
    if (e < E) atomicAdd(&d_deg[ei[E + e]], 1);
}

// Block sums of deg (1024/block)
__global__ void k_bsum(int n) {
    __shared__ int ws[32];
    int t = threadIdx.x, lane = t & 31, wid = t >> 5;
    int i = blockIdx.x * 1024 + t;
    int v = (i < n) ? d_deg[i] : 0;
    int s = warpSumI(v);
    if (lane == 0) ws[wid] = s;
    __syncthreads();
    if (wid == 0) {
        int u = ws[lane];
        u = warpSumI(u);
        if (lane == 0) d_bsum[blockIdx.x] = u;
    }
}

// Exclusive scan of block sums (nb <= 128)
__global__ void k_scanb(int nb) {
    __shared__ int ws[4];
    int t = threadIdx.x, lane = t & 31, wid = t >> 5;
    int v = (t < nb) ? d_bsum[t] : 0;
    int inc = warpIncScan(v, lane);
    if (lane == 31) ws[wid] = inc;
    __syncthreads();
    int off = 0;
#pragma unroll
    for (int k = 0; k < 4; ++k) off += (k < wid) ? ws[k] : 0;
    if (t < nb) d_bsum[t] = off + inc - v;   // exclusive
}

// Full exclusive scan -> d_start
__global__ void k_start(int n) {
    __shared__ int ws[32];
    int t = threadIdx.x, lane = t & 31, wid = t >> 5;
    int i = blockIdx.x * 1024 + t;
    int v = (i < n) ? d_deg[i] : 0;
    int inc = warpIncScan(v, lane);
    if (lane == 31) ws[wid] = inc;
    __syncthreads();
    if (wid == 0) {
        int s = ws[lane];
        int si = warpIncScan(s, lane);
        ws[lane] = si - s;                   // exclusive warp offsets
    }
    __syncthreads();
    if (i < n) d_start[i] = d_bsum[blockIdx.x] + ws[wid] + inc - v;
}

__global__ void k_scatter(const int* __restrict__ ei, int E) {
    int e = blockIdx.x * blockDim.x + threadIdx.x;
    if (e < E) {
        int r = ei[e];
        int c = ei[E + e];
        int pos = d_start[c] + atomicAdd(&d_cur[c], 1);
        d_srcs[pos] = r;
    }
}

// ---------------------------------------------------------------------------
// Main aggregation: one warp per target node. Chunked (32-edge) softmax:
// lane-parallel weight computation, then per-edge broadcast + float2 gather.
__global__ void k_agg(const float* __restrict__ x, float* __restrict__ out, int n) {
    int node = (blockIdx.x * blockDim.x + threadIdx.x) >> 5;
    int lane = threadIdx.x & 31;
    if (node >= n) return;

    int s0  = d_start[node];
    int deg = d_deg[node];

    float m  = -INFINITY;
    float zl = 0.0f;
    float2 A = make_float2(0.0f, 0.0f);   // sum w * x_src
    float2 T = make_float2(0.0f, 0.0f);   // sum w * coef_src * x_src

    for (int c = 0; c < deg; c += 32) {
        int cnt = min(32, deg - c);
        bool val = lane < cnt;
        int src = val ? d_srcs[s0 + c + lane] : 0;
        float2 gs = val ? d_gc[src] : make_float2(-INFINITY, 0.0f);

        // chunk max + rescale (g_col cancels in the softmax)
        float cm = warpMaxF(gs.x);
        float nm = fmaxf(m, cm);
        float r  = __expf(m - nm);                 // 0 on first chunk
        zl *= r; A.x *= r; A.y *= r; T.x *= r; T.y *= r;
        m = nm;

        float w  = val ? __expf(gs.x - m) : 0.0f;
        zl += w;
        float wc = w * gs.y;

#pragma unroll 4
        for (int i = 0; i < cnt; ++i) {
            float wi  = __shfl_sync(0xffffffffu, w,   i);
            float wci = __shfl_sync(0xffffffffu, wc,  i);
            int   si  = __shfl_sync(0xffffffffu, src, i);
            float2 v = *reinterpret_cast<const float2*>(x + (size_t)si * 64 + lane * 2);
            A.x += wi  * v.x;  A.y += wi  * v.y;
            T.x += wci * v.x;  T.y += wci * v.y;
        }
    }

    float z = warpSumF(zl);
    bool isolated = (deg == 0);
    float invz = isolated ? 0.0f : (1.0f / z);

    float2 agg = make_float2(A.x * invz, A.y * invz);
    float2 tan = make_float2(T.x * invz, T.y * invz);
    if (lane == 0) tan.x = 0.0f;                   // tangent time component = 0

    // nsq = -<agg,agg>_L
    float cterm = agg.x * agg.x + agg.y * agg.y;
    if (lane == 0) cterm = -agg.x * agg.x + agg.y * agg.y;
    float mdot = warpSumF(cterm);
    float nsq = -mdot;
    bool non_timelike = (nsq <= 1e-8f);

    // tangent fallback: fb = cosh(vn)*e0 + sinh(vn)/vn * tan
    float t2 = tan.x * tan.x + tan.y * tan.y;
    float vnsq = warpSumF(t2);
    float vn = sqrtf(fmaxf(vnsq, 1e-15f));
    float sh = sinhf(vn) / vn;
    float ch = coshf(vn);
    float2 fb = make_float2(sh * tan.x, sh * tan.y);
    if (lane == 0) fb.x = ch;

    float2 a2 = non_timelike ? fb : agg;

    float c2 = a2.x * a2.x + a2.y * a2.y;
    if (lane == 0) c2 = -a2.x * a2.x + a2.y * a2.y;
    float mdot2 = warpSumF(c2);
    float nsq2 = -mdot2;
    float denom = fmaxf(sqrtf(fmaxf(nsq2, 0.0f)), 1e-12f);
    float inv = 1.0f / denom;

    float a20 = __shfl_sync(0xffffffffu, a2.x, 0);
    float fac = (a20 <= 0.0f) ? -inv : inv;        // upper-sheet correction

    float2 o = make_float2(a2.x * fac, a2.y * fac);
    *reinterpret_cast<float2*>(out + (size_t)node * 64 + lane * 2) = o;
}

// ---------------------------------------------------------------------------
extern "C" void kernel_launch(void* const* d_in, const int* in_sizes, int n_in,
                              void* d_out, int out_size) {
    const float* x  = (const float*)d_in[0];
    const int*   ei = (const int*)d_in[1];
    const float* aw = (const float*)d_in[2];
    float* out = (float*)d_out;

    int N = in_sizes[0] / 64;
    int E = in_sizes[1] / 2;
    int nb = (N + 1023) / 1024;

    k_pre    <<<(N + 7) / 8,     256>>>(x, aw, N);
    k_count  <<<(E + 255) / 256, 256>>>(ei, E);
    k_bsum   <<<nb,             1024>>>(N);
    k_scanb  <<<1,               128>>>(nb);
    k_start  <<<nb,             1024>>>(N);
    k_scatter<<<(E + 255) / 256, 256>>>(ei, E);
    k_agg    <<<(N + 7) / 8,     256>>>(x, out, N);
}